// round 1
// baseline (speedup 1.0000x reference)
#include <cuda_runtime.h>
#include <cuda_bf16.h>

// Problem constants
#define NROWS 65536
#define DDIM  64
#define KEMB  8192
#define BM    64
#define BN    64
#define TM    4
#define TN    4
#define NTHREADS 256           // 16x16 thread grid
#define NTILES (KEMB / BN)     // 128

// Output layout (flattened, concat in return order, fp32):
//   [0, N*D)           quantized
//   [N*D]              vq_loss
//   [N*D+1]            commitment_loss
//   [N*D+2, N*D+2+N)   encoding_indices (float)
#define OUT_LOSS   (NROWS * DDIM)
#define OUT_IDX    (NROWS * DDIM + 2)

#define NPARTIAL 1024

// Scratch (no allocations allowed)
__device__ float g_esq[KEMB];
__device__ int   g_idx[NROWS];
__device__ float g_partial[NPARTIAL];

// ---------------------------------------------------------------------------
// Kernel 1: e_sq[k] = sum_d emb[k][d]^2  (sequential order, fp32)
// ---------------------------------------------------------------------------
__global__ void esq_kernel(const float* __restrict__ E) {
    int k = blockIdx.x * blockDim.x + threadIdx.x;
    if (k < KEMB) {
        const float* row = E + k * DDIM;
        float s = 0.f;
#pragma unroll
        for (int d = 0; d < DDIM; d++) {
            float v = row[d];
            s += v * v;
        }
        g_esq[k] = s;
    }
}

// ---------------------------------------------------------------------------
// Kernel 2: per-row argmin over K of d2 = (z_sq - 2*dot) + e_sq
// CTA: 64 rows x 256 threads; loops 128 tiles of 64 embeddings.
// ---------------------------------------------------------------------------
__global__ __launch_bounds__(NTHREADS) void vq_argmin_kernel(
    const float* __restrict__ Z, const float* __restrict__ E)
{
    __shared__ float Zs[DDIM][BM];   // [d][m]
    __shared__ float Es[DDIM][BN];   // [d][n]
    __shared__ float zsq_s[BM];

    const int tid = threadIdx.x;
    const int tx  = tid & 15;        // column group 0..15
    const int ty  = tid >> 4;        // row group 0..15
    const int rowBase = blockIdx.x * BM;

    // Loader mapping: thread handles column m, d-chunk dc (16 d's, 4 float4s)
    const int lm = tid & 63;
    const int dc = tid >> 6;         // 0..3

    // ---- stage Z tile transposed ----
    {
        const float4* zp = reinterpret_cast<const float4*>(
            Z + (size_t)(rowBase + lm) * DDIM + dc * 16);
#pragma unroll
        for (int j = 0; j < 4; j++) {
            float4 v = zp[j];
            int d0 = dc * 16 + j * 4;
            Zs[d0 + 0][lm] = v.x;
            Zs[d0 + 1][lm] = v.y;
            Zs[d0 + 2][lm] = v.z;
            Zs[d0 + 3][lm] = v.w;
        }
    }
    __syncthreads();

    // ---- z_sq per row (sequential over d, matches jnp.sum order) ----
    if (tid < BM) {
        float s = 0.f;
#pragma unroll
        for (int d = 0; d < DDIM; d++) {
            float v = Zs[d][tid];
            s += v * v;
        }
        zsq_s[tid] = s;
    }
    __syncthreads();

    float zsq[TM];
#pragma unroll
    for (int i = 0; i < TM; i++) zsq[i] = zsq_s[ty * TM + i];

    float bestv[TM];
    int   besti[TM];
#pragma unroll
    for (int i = 0; i < TM; i++) { bestv[i] = 3.4e38f; besti[i] = 0; }

    // ---- prefetch first E tile into registers ----
    float4 pre[4];
    {
        const float4* ep = reinterpret_cast<const float4*>(
            E + (size_t)lm * DDIM + dc * 16);
#pragma unroll
        for (int j = 0; j < 4; j++) pre[j] = ep[j];
    }

    for (int kt = 0; kt < NTILES; kt++) {
        // store prefetched tile (transposed) into smem
#pragma unroll
        for (int j = 0; j < 4; j++) {
            int d0 = dc * 16 + j * 4;
            Es[d0 + 0][lm] = pre[j].x;
            Es[d0 + 1][lm] = pre[j].y;
            Es[d0 + 2][lm] = pre[j].z;
            Es[d0 + 3][lm] = pre[j].w;
        }
        __syncthreads();

        // issue prefetch of next tile (latency hides under the FMA block)
        if (kt + 1 < NTILES) {
            const float4* ep = reinterpret_cast<const float4*>(
                E + (size_t)((kt + 1) * BN + lm) * DDIM + dc * 16);
#pragma unroll
            for (int j = 0; j < 4; j++) pre[j] = ep[j];
        }

        float acc[TM][TN];
#pragma unroll
        for (int i = 0; i < TM; i++)
#pragma unroll
            for (int j = 0; j < TN; j++) acc[i][j] = 0.f;

#pragma unroll
        for (int d = 0; d < DDIM; d++) {
            float4 av = *reinterpret_cast<const float4*>(&Zs[d][ty * TM]);
            float4 bv = *reinterpret_cast<const float4*>(&Es[d][tx * TN]);
            float a[TM] = {av.x, av.y, av.z, av.w};
            float b[TN] = {bv.x, bv.y, bv.z, bv.w};
#pragma unroll
            for (int i = 0; i < TM; i++)
#pragma unroll
                for (int j = 0; j < TN; j++)
                    acc[i][j] = fmaf(a[i], b[j], acc[i][j]);
        }

        // epilogue: d2 = fl(fl(z_sq - 2*dot) + e_sq), running min (strict <)
        const int colBase = kt * BN + tx * TN;
#pragma unroll
        for (int j = 0; j < TN; j++) {
            float es = g_esq[colBase + j];
#pragma unroll
            for (int i = 0; i < TM; i++) {
                float t  = fmaf(-2.0f, acc[i][j], zsq[i]); // one rounding, 2*dot exact
                float d2 = t + es;                          // second rounding
                if (d2 < bestv[i]) { bestv[i] = d2; besti[i] = colBase + j; }
            }
        }
        __syncthreads();
    }

    // ---- cross-thread reduction over the 16 tx lanes (same 16-lane segment) ----
#pragma unroll
    for (int i = 0; i < TM; i++) {
        float v = bestv[i];
        int   x = besti[i];
#pragma unroll
        for (int off = 8; off >= 1; off >>= 1) {
            float ov = __shfl_down_sync(0xFFFFFFFFu, v, off, 16);
            int   ox = __shfl_down_sync(0xFFFFFFFFu, x, off, 16);
            if (ov < v || (ov == v && ox < x)) { v = ov; x = ox; }
        }
        if (tx == 0) g_idx[rowBase + ty * TM + i] = x;
    }
}

// ---------------------------------------------------------------------------
// Kernel 3: gather quantized = emb[idx], partial loss sums, index-as-float
// grid 1024 x 256, each thread 4 float4 elements (covers N*D exactly)
// ---------------------------------------------------------------------------
__global__ __launch_bounds__(256) void gather_loss_kernel(
    const float* __restrict__ Z, const float* __restrict__ E,
    float* __restrict__ out)
{
    __shared__ float red[256];
    const int tid  = threadIdx.x;
    const int gtid = blockIdx.x * blockDim.x + tid;

    float lsum = 0.f;
    const float4* Z4 = reinterpret_cast<const float4*>(Z);
    float4* O4 = reinterpret_cast<float4*>(out);

#pragma unroll
    for (int j = 0; j < 4; j++) {
        int f   = gtid * 4 + j;           // float4 index, < N*D/4
        int row = f >> 4;                 // 16 float4 per row
        int dc  = (f & 15);
        int idx = g_idx[row];
        const float4* E4 = reinterpret_cast<const float4*>(E + (size_t)idx * DDIM);
        float4 q = E4[dc];
        float4 z = Z4[f];
        O4[f] = q;
        float dx = z.x - q.x, dy = z.y - q.y, dz = z.z - q.z, dw = z.w - q.w;
        lsum += dx * dx + dy * dy + dz * dz + dw * dw;
    }

    // encoding indices as float
    if (gtid < NROWS) out[OUT_IDX + gtid] = (float)g_idx[gtid];

    // deterministic block tree reduction
    red[tid] = lsum;
    __syncthreads();
    for (int s = 128; s > 0; s >>= 1) {
        if (tid < s) red[tid] += red[tid + s];
        __syncthreads();
    }
    if (tid == 0) g_partial[blockIdx.x] = red[0];
}

// ---------------------------------------------------------------------------
// Kernel 4: finalize losses (single block, deterministic)
// ---------------------------------------------------------------------------
__global__ __launch_bounds__(512) void finalize_kernel(float* __restrict__ out) {
    __shared__ float red[512];
    int tid = threadIdx.x;
    red[tid] = g_partial[tid] + g_partial[tid + 512];
    __syncthreads();
    for (int s = 256; s > 0; s >>= 1) {
        if (tid < s) red[tid] += red[tid + s];
        __syncthreads();
    }
    if (tid == 0) {
        float loss = red[0] * (1.0f / (float)(NROWS * DDIM)); // N*D = 2^22, exact
        out[OUT_LOSS + 0] = loss;   // vq_loss
        out[OUT_LOSS + 1] = loss;   // commitment_loss (identical forward value)
    }
}

// ---------------------------------------------------------------------------
extern "C" void kernel_launch(void* const* d_in, const int* in_sizes, int n_in,
                              void* d_out, int out_size)
{
    const float* Z = (const float*)d_in[0];
    const float* E = (const float*)d_in[1];
    // defensive: metadata order is (z_feats [N*D], emb [K*D])
    if (n_in >= 2 && in_sizes[0] == KEMB * DDIM && in_sizes[1] == NROWS * DDIM) {
        const float* t = Z; Z = E; E = t;
    }
    float* out = (float*)d_out;

    esq_kernel<<<KEMB / 256, 256>>>(E);
    vq_argmin_kernel<<<NROWS / BM, NTHREADS>>>(Z, E);
    gather_loss_kernel<<<NPARTIAL, 256>>>(Z, E, out);
    finalize_kernel<<<1, 512>>>(out);
}